// round 14
// baseline (speedup 1.0000x reference)
#include <cuda_runtime.h>
#include <cuda_fp16.h>
#include <cstdint>

// Fixed shapes
#define B 2
#define D 160
#define H 160
#define W 160
#define NVOX (B * D * H * W)          // 8,192,000
#define HW (H * W)                    // 25,600

#define HSEGS 4
#define HSEG_LEN (H / HSEGS)          // 40
#define A_BLOCKS (B * D * HSEGS)      // 1280
#define KA_THREADS 80                 // one float2 (2 outputs) per thread
#define SROW 172                      // 6 pad + 160 + 6 pad

#define KB_SEGS 10
#define KB_SEGLEN (D / KB_SEGS)       // 16
#define KB_HBLK 2
#define KB_THREADS 80                 // 40 half4-lanes x 2 h-rows
#define KB_BLOCKS (B * (H / KB_HBLK) * KB_SEGS)  // 1600

// SSIM constants (faithful: C1 = K1 / data_range^2)
#define C1F 5.9604644775390625e-10f   // 0.01 / 4096^2
#define C2F 1.7881393432617188e-09f   // 0.03 / 4096^2
#define INV_WIN3 (1.0f / 1331.0f)

// Intermediate: 5 quantity planes, fp16 packed as half2 (w-pairs).
__device__ __half2 g_bufB[5 * (NVOX / 2)];
__device__ float g_l1part[A_BLOCKS];
__device__ float g_ssimpart[KB_BLOCKS];

__device__ __forceinline__ void cp_async8(uint32_t saddr, const void* g) {
    asm volatile("cp.async.ca.shared.global [%0], [%1], 8;" :: "r"(saddr), "l"(g));
}
__device__ __forceinline__ void cp_commit() {
    asm volatile("cp.async.commit_group;");
}
__device__ __forceinline__ void cp_wait2() {
    asm volatile("cp.async.wait_group 2;");
}

// ---------------------------------------------------------------------------
// Kernel A: fused W+H box sums (x, y, x^2, y^2, xy), 2 outputs per thread.
// 11-slot cp.async staging pipeline (depth 3), float2 taps, incremental
// second output, fp32 register ring. Output stored as half2.
// EXACT R12 config (measured 47.5us twice). min-blocks 4 = regfile ceiling.
// ---------------------------------------------------------------------------
#define KA_FETCH(ROW, SLOT) { \
    const int _r = (ROW); \
    if (_r >= 0 && _r < H) { \
        cp_async8(sx_base + (SLOT) * (SROW * 4) + (6 + w) * 4, x + pb + _r * W + w); \
        cp_async8(sy_base + (SLOT) * (SROW * 4) + (6 + w) * 4, y + pb + _r * W + w); \
    } else { \
        *(float2*)&sx[SLOT][6 + w] = make_float2(0.f, 0.f); \
        *(float2*)&sy[SLOT][6 + w] = make_float2(0.f, 0.f); \
    } \
    cp_commit(); }

#define KA_STEP(TT) { \
    cp_wait2(); \
    __syncthreads(); \
    { \
        const float2* rx2 = (const float2*)&sx[TT][w]; \
        const float2* ry2 = (const float2*)&sy[TT][w]; \
        float xv[14], yv[14]; \
        _Pragma("unroll") \
        for (int i = 0; i < 7; i++) { \
            float2 t2 = rx2[i]; xv[2*i] = t2.x; xv[2*i+1] = t2.y; \
            float2 u2 = ry2[i]; yv[2*i] = u2.x; yv[2*i+1] = u2.y; \
        } \
        float ax = xv[1], ay = yv[1]; \
        float axx = xv[1]*xv[1], ayy = yv[1]*yv[1], axy = xv[1]*yv[1]; \
        _Pragma("unroll") \
        for (int i = 2; i <= 11; i++) { \
            ax += xv[i]; ay += yv[i]; \
            axx = fmaf(xv[i], xv[i], axx); \
            ayy = fmaf(yv[i], yv[i], ayy); \
            axy = fmaf(xv[i], yv[i], axy); \
        } \
        float dax = xv[12] - xv[1], day = yv[12] - yv[1]; \
        float ax1 = ax + dax, ay1 = ay + day; \
        float axx1 = fmaf(dax, xv[12] + xv[1], axx); \
        float ayy1 = fmaf(day, yv[12] + yv[1], ayy); \
        float axy1 = fmaf(-xv[1], yv[1], fmaf(xv[12], yv[12], axy)); \
        rg0[TT] = make_float2(ax, ax1);   s0.x += ax;  s0.y += ax1; \
        rg1[TT] = make_float2(ay, ay1);   s1.x += ay;  s1.y += ay1; \
        rg2[TT] = make_float2(axx, axx1); s2.x += axx; s2.y += axx1; \
        rg3[TT] = make_float2(ayy, ayy1); s3.x += ayy; s3.y += ayy1; \
        rg4[TT] = make_float2(axy, axy1); s4.x += axy; s4.y += axy1; \
        if (r >= h0 && r < h1) { \
            float e0 = fabsf(xv[6] - yv[6]); \
            l1acc += (e0 < 1.f) ? 0.5f * e0 * e0 : e0 - 0.5f; \
            float e1 = fabsf(xv[7] - yv[7]); \
            l1acc += (e1 < 1.f) ? 0.5f * e1 * e1 : e1 - 0.5f; \
        } \
    } \
    KA_FETCH(r + 3, (TT + 3) % 11) \
    if (t >= 10) { \
        const int hh = h0 + t - 10; \
        const int o2 = (pb + hh * W + w) >> 1; \
        g_bufB[0 * (NVOX/2) + o2] = __float22half2_rn(s0); \
        g_bufB[1 * (NVOX/2) + o2] = __float22half2_rn(s1); \
        g_bufB[2 * (NVOX/2) + o2] = __float22half2_rn(s2); \
        g_bufB[3 * (NVOX/2) + o2] = __float22half2_rn(s3); \
        g_bufB[4 * (NVOX/2) + o2] = __float22half2_rn(s4); \
        float2 z; \
        z = rg0[(TT + 1) % 11]; s0.x -= z.x; s0.y -= z.y; \
        z = rg1[(TT + 1) % 11]; s1.x -= z.x; s1.y -= z.y; \
        z = rg2[(TT + 1) % 11]; s2.x -= z.x; s2.y -= z.y; \
        z = rg3[(TT + 1) % 11]; s3.x -= z.x; s3.y -= z.y; \
        z = rg4[(TT + 1) % 11]; s4.x -= z.x; s4.y -= z.y; \
    } \
    r++; t++; }

__global__ __launch_bounds__(KA_THREADS, 4) void kA_wh(const float* __restrict__ x,
                                                       const float* __restrict__ y) {
    __shared__ __align__(16) float sx[11][SROW];
    __shared__ __align__(16) float sy[11][SROW];
    __shared__ float red[KA_THREADS];

    const int bx = blockIdx.x;
    const int seg = bx % HSEGS;
    const int d = (bx / HSEGS) % D;
    const int b = bx / (HSEGS * D);
    const int w2 = threadIdx.x;        // 0..79
    const int w = 2 * w2;

    const int h0 = seg * HSEG_LEN;
    const int h1 = h0 + HSEG_LEN;
    const int pb = (b * D + d) * HW;

    const uint32_t sx_base = (uint32_t)__cvta_generic_to_shared(&sx[0][0]);
    const uint32_t sy_base = (uint32_t)__cvta_generic_to_shared(&sy[0][0]);

    // zero pads once (cp.async never touches indices 0..5 / 166..171)
    if (w2 < 12) {
        int p = (w2 < 6) ? w2 : (160 + w2);
#pragma unroll
        for (int s = 0; s < 11; s++) { sx[s][p] = 0.f; sy[s][p] = 0.f; }
    }

    // prologue: fetch rows h0-5 .. h0-3 into slots 0..2
    KA_FETCH(h0 - 5, 0)
    KA_FETCH(h0 - 4, 1)
    KA_FETCH(h0 - 3, 2)

    float2 s0 = {0.f, 0.f}, s1 = {0.f, 0.f}, s2 = {0.f, 0.f};
    float2 s3 = {0.f, 0.f}, s4 = {0.f, 0.f};
    float l1acc = 0.f;
    float2 rg0[11], rg1[11], rg2[11], rg3[11], rg4[11];
    int r = h0 - 5;
    int t = 0;

#pragma unroll 1
    for (int tc = 0; tc < 4; tc++) {
        KA_STEP(0) KA_STEP(1) KA_STEP(2) KA_STEP(3) KA_STEP(4) KA_STEP(5)
        KA_STEP(6) KA_STEP(7) KA_STEP(8) KA_STEP(9) KA_STEP(10)
    }
    KA_STEP(0) KA_STEP(1) KA_STEP(2) KA_STEP(3) KA_STEP(4) KA_STEP(5)

    // deterministic block reduction of l1acc over 80 threads
    red[w2] = l1acc;
    __syncthreads();
    if (w2 < 40) red[w2] += red[w2 + 40];
    __syncthreads();
    if (w2 < 20) red[w2] += red[w2 + 20];
    __syncthreads();
    if (w2 < 10) red[w2] += red[w2 + 10];
    __syncthreads();
    if (w2 < 5) red[w2] += red[w2 + 5];
    __syncthreads();
    if (w2 == 0) {
        g_l1part[bx] = red[0] + red[1] + red[2] + red[3] + red[4];
    }
}
#undef KA_STEP
#undef KA_FETCH

// ---------------------------------------------------------------------------
// SSIM numerator/denominator (no division)
// ---------------------------------------------------------------------------
__device__ __forceinline__ void ssim_nd(float s0, float s1, float s2,
                                        float s3, float s4,
                                        float& num, float& den) {
    float mux = s0 * INV_WIN3;
    float muy = s1 * INV_WIN3;
    float mux2 = mux * mux;
    float muy2 = muy * muy;
    float muxy = mux * muy;
    float sxx = s2 * INV_WIN3 - mux2;
    float syy = s3 * INV_WIN3 - muy2;
    float sxy = s4 * INV_WIN3 - muxy;
    num = (2.f * muxy + C1F) * (2.f * sxy + C2F);
    den = (mux2 + muy2 + C1F) * (sxx + syy + C2F) + 1e-8f;
}

__device__ __forceinline__ float clip_loss(float ssim) {
    float loss = (1.f - ssim) * 0.5f;
    return fminf(fmaxf(loss, 0.f), 1.f);
}

// half4 load (uint2) -> float4
__device__ __forceinline__ float4 ldh4(const __half2* p) {
    uint2 u = *reinterpret_cast<const uint2*>(p);
    __half2 h0 = *reinterpret_cast<__half2*>(&u.x);
    __half2 h1 = *reinterpret_cast<__half2*>(&u.y);
    float2 f0 = __half22float2(h0);
    float2 f1 = __half22float2(h1);
    return make_float4(f0.x, f0.y, f1.x, f1.y);
}

#define ACC4(S, V) { S.x += V.x; S.y += V.y; S.z += V.z; S.w += V.w; }
#define UPD4(S, A, Bv) { S.x += A.x - Bv.x; S.y += A.y - Bv.y; \
                         S.z += A.z - Bv.z; S.w += A.w - Bv.w; }

// ---------------------------------------------------------------------------
// Kernel B: box-sum along D + SSIM (Montgomery batched reciprocal) + block
// reduction. half4 loads, 4 w-outputs per thread, 2 h-rows/block, 16-deep
// d segments. Manually software-pipelined: step i+1's edge loads are issued
// BEFORE step i's SSIM math so their latency overlaps compute.
// grid = 1600, 80 threads.
// ---------------------------------------------------------------------------
#define KB_LOAD(ii) { \
    const int _dn = d0 + (ii) + 6; \
    const int _dp = d0 + (ii) - 5; \
    na0 = make_float4(0,0,0,0); na1 = na0; na2 = na0; na3 = na0; na4 = na0; \
    nb0 = na0; nb1 = na0; nb2 = na0; nb3 = na0; nb4 = na0; \
    if (_dn < D) { \
        const int id = colh2 + _dn * sth2; \
        na0 = ldh4(q0 + id); na1 = ldh4(q1 + id); na2 = ldh4(q2 + id); \
        na3 = ldh4(q3 + id); na4 = ldh4(q4 + id); \
    } \
    if (_dp >= 0) { \
        const int id = colh2 + _dp * sth2; \
        nb0 = ldh4(q0 + id); nb1 = ldh4(q1 + id); nb2 = ldh4(q2 + id); \
        nb3 = ldh4(q3 + id); nb4 = ldh4(q4 + id); \
    } }

__global__ __launch_bounds__(KB_THREADS) void kB_dpass_ssim() {
    __shared__ float red[KB_THREADS];

    const int bid = blockIdx.x;
    const int seg = bid % KB_SEGS;
    const int hq = (bid / KB_SEGS) % (H / KB_HBLK);
    const int b = bid / (KB_SEGS * (H / KB_HBLK));

    const int tid = threadIdx.x;
    const int lane = tid % (W / 4);    // 0..39, 4-wide w chunk
    const int row = tid / (W / 4);     // 0..1
    const int h = hq * KB_HBLK + row;

    const int d0 = seg * KB_SEGLEN;
    const int colh2 = (b * (D * HW) + h * W) / 2 + lane * 2;  // half2 units
    const int sth2 = HW / 2;

    const __half2* __restrict__ q0 = g_bufB + 0 * (NVOX / 2);
    const __half2* __restrict__ q1 = g_bufB + 1 * (NVOX / 2);
    const __half2* __restrict__ q2 = g_bufB + 2 * (NVOX / 2);
    const __half2* __restrict__ q3 = g_bufB + 3 * (NVOX / 2);
    const __half2* __restrict__ q4 = g_bufB + 4 * (NVOX / 2);

    float4 s0 = {0,0,0,0}, s1 = {0,0,0,0}, s2 = {0,0,0,0};
    float4 s3 = {0,0,0,0}, s4 = {0,0,0,0};
    {
        int lo = d0 - 5; if (lo < 0) lo = 0;
        int hi = d0 + 5; if (hi > D - 1) hi = D - 1;
        for (int d = lo; d <= hi; d++) {
            int id = colh2 + d * sth2;
            float4 v;
            v = ldh4(q0 + id); ACC4(s0, v)
            v = ldh4(q1 + id); ACC4(s1, v)
            v = ldh4(q2 + id); ACC4(s2, v)
            v = ldh4(q3 + id); ACC4(s3, v)
            v = ldh4(q4 + id); ACC4(s4, v)
        }
    }

    // pipeline registers for next step's edges
    float4 na0, na1, na2, na3, na4;
    float4 nb0, nb1, nb2, nb3, nb4;
    KB_LOAD(0)

    float acc = 0.f;
#pragma unroll 4
    for (int i = 0; i < KB_SEGLEN; i++) {
        // retire prefetched edges into current-step regs
        float4 ca0 = na0, ca1 = na1, ca2 = na2, ca3 = na3, ca4 = na4;
        float4 cb0 = nb0, cb1 = nb1, cb2 = nb2, cb3 = nb3, cb4 = nb4;

        // issue next step's loads BEFORE the math (overlap latency)
        if (i + 1 < KB_SEGLEN) KB_LOAD(i + 1)

        // 4 SSIM ratios with a single reciprocal (Montgomery batch inversion)
        {
            float nA, dA, nB, dB, nC, dC, nD, dD;
            ssim_nd(s0.x, s1.x, s2.x, s3.x, s4.x, nA, dA);
            ssim_nd(s0.y, s1.y, s2.y, s3.y, s4.y, nB, dB);
            ssim_nd(s0.z, s1.z, s2.z, s3.z, s4.z, nC, dC);
            ssim_nd(s0.w, s1.w, s2.w, s3.w, s4.w, nD, dD);
            float dAB = dA * dB;
            float dCD = dC * dD;
            float r = __fdividef(1.0f, dAB * dCD);
            float ssimA = nA * (dB * dCD) * r;
            float ssimB = nB * (dA * dCD) * r;
            float ssimC = nC * (dAB * dD) * r;
            float ssimD = nD * (dAB * dC) * r;
            acc += clip_loss(ssimA);
            acc += clip_loss(ssimB);
            acc += clip_loss(ssimC);
            acc += clip_loss(ssimD);
        }

        UPD4(s0, ca0, cb0)
        UPD4(s1, ca1, cb1)
        UPD4(s2, ca2, cb2)
        UPD4(s3, ca3, cb3)
        UPD4(s4, ca4, cb4)
    }

    // deterministic block reduction over 80 threads
    red[tid] = acc;
    __syncthreads();
    if (tid < 40) red[tid] += red[tid + 40];
    __syncthreads();
    if (tid < 20) red[tid] += red[tid + 20];
    __syncthreads();
    if (tid < 10) red[tid] += red[tid + 10];
    __syncthreads();
    if (tid < 5) red[tid] += red[tid + 5];
    __syncthreads();
    if (tid == 0) {
        g_ssimpart[bid] = red[0] + red[1] + red[2] + red[3] + red[4];
    }
}
#undef KB_LOAD

// ---------------------------------------------------------------------------
// Kernel C: final deterministic reduction.
// ---------------------------------------------------------------------------
__global__ __launch_bounds__(256) void kC_final(float* __restrict__ out) {
    __shared__ double sh[256];
    const int t = threadIdx.x;

    double a = 0.0;
    for (int i = t; i < A_BLOCKS; i += 256) a += (double)g_l1part[i];
    double bsum = 0.0;
    for (int i = t; i < KB_BLOCKS; i += 256) bsum += (double)g_ssimpart[i];

    sh[t] = a;
    __syncthreads();
#pragma unroll
    for (int s = 128; s > 0; s >>= 1) {
        if (t < s) sh[t] += sh[t + s];
        __syncthreads();
    }
    double l1sum = sh[0];
    __syncthreads();

    sh[t] = bsum;
    __syncthreads();
#pragma unroll
    for (int s = 128; s > 0; s >>= 1) {
        if (t < s) sh[t] += sh[t + s];
        __syncthreads();
    }

    if (t == 0) {
        double ssimsum = sh[0];
        double n = (double)NVOX;
        out[0] = (float)(0.85 * (ssimsum / n) + 0.15 * (l1sum / n));
    }
}

// ---------------------------------------------------------------------------
extern "C" void kernel_launch(void* const* d_in, const int* in_sizes, int n_in,
                              void* d_out, int out_size) {
    const float* pred = (const float*)d_in[0];
    const float* target = (const float*)d_in[1];
    float* out = (float*)d_out;

    kA_wh<<<A_BLOCKS, KA_THREADS>>>(pred, target);
    kB_dpass_ssim<<<KB_BLOCKS, KB_THREADS>>>();
    kC_final<<<1, 256>>>(out);
}

// round 15
// speedup vs baseline: 1.1448x; 1.1448x over previous
#include <cuda_runtime.h>
#include <cuda_fp16.h>
#include <cstdint>

// Fixed shapes
#define B 2
#define D 160
#define H 160
#define W 160
#define NVOX (B * D * H * W)          // 8,192,000
#define HW (H * W)                    // 25,600

#define HSEGS 4
#define HSEG_LEN (H / HSEGS)          // 40
#define A_BLOCKS (B * D * HSEGS)      // 1280
#define KA_THREADS 80                 // one float2 (2 outputs) per thread
#define SROW 172                      // 6 pad + 160 + 6 pad

#define KB_SEGS 5
#define KB_SEGLEN (D / KB_SEGS)       // 32
#define KB_HBLK 2
#define KB_THREADS 160                // 80 half2-lanes x 2 h-rows
#define KB_BLOCKS (B * (H / KB_HBLK) * KB_SEGS)  // 800

// SSIM constants (faithful: C1 = K1 / data_range^2)
#define C1F 5.9604644775390625e-10f   // 0.01 / 4096^2
#define C2F 1.7881393432617188e-09f   // 0.03 / 4096^2
#define INV_WIN3 (1.0f / 1331.0f)

// Intermediate: 5 quantity planes, fp16 packed as half2 (w-pairs).
__device__ __half2 g_bufB[5 * (NVOX / 2)];
__device__ float g_l1part[A_BLOCKS];
__device__ float g_ssimpart[KB_BLOCKS];

__device__ __forceinline__ void cp_async8(uint32_t saddr, const void* g) {
    asm volatile("cp.async.ca.shared.global [%0], [%1], 8;" :: "r"(saddr), "l"(g));
}
__device__ __forceinline__ void cp_commit() {
    asm volatile("cp.async.commit_group;");
}
__device__ __forceinline__ void cp_wait2() {
    asm volatile("cp.async.wait_group 2;");
}

// ---------------------------------------------------------------------------
// Kernel A: fused W+H box sums (x, y, x^2, y^2, xy), 2 outputs per thread.
// 11-slot cp.async staging pipeline (depth 3), float2 taps, incremental
// second output, fp32 register ring. Output stored as half2.
// FROZEN R12 config (measured 47.1-47.5us across 4 rounds).
// ---------------------------------------------------------------------------
#define KA_FETCH(ROW, SLOT) { \
    const int _r = (ROW); \
    if (_r >= 0 && _r < H) { \
        cp_async8(sx_base + (SLOT) * (SROW * 4) + (6 + w) * 4, x + pb + _r * W + w); \
        cp_async8(sy_base + (SLOT) * (SROW * 4) + (6 + w) * 4, y + pb + _r * W + w); \
    } else { \
        *(float2*)&sx[SLOT][6 + w] = make_float2(0.f, 0.f); \
        *(float2*)&sy[SLOT][6 + w] = make_float2(0.f, 0.f); \
    } \
    cp_commit(); }

#define KA_STEP(TT) { \
    cp_wait2(); \
    __syncthreads(); \
    { \
        const float2* rx2 = (const float2*)&sx[TT][w]; \
        const float2* ry2 = (const float2*)&sy[TT][w]; \
        float xv[14], yv[14]; \
        _Pragma("unroll") \
        for (int i = 0; i < 7; i++) { \
            float2 t2 = rx2[i]; xv[2*i] = t2.x; xv[2*i+1] = t2.y; \
            float2 u2 = ry2[i]; yv[2*i] = u2.x; yv[2*i+1] = u2.y; \
        } \
        float ax = xv[1], ay = yv[1]; \
        float axx = xv[1]*xv[1], ayy = yv[1]*yv[1], axy = xv[1]*yv[1]; \
        _Pragma("unroll") \
        for (int i = 2; i <= 11; i++) { \
            ax += xv[i]; ay += yv[i]; \
            axx = fmaf(xv[i], xv[i], axx); \
            ayy = fmaf(yv[i], yv[i], ayy); \
            axy = fmaf(xv[i], yv[i], axy); \
        } \
        float dax = xv[12] - xv[1], day = yv[12] - yv[1]; \
        float ax1 = ax + dax, ay1 = ay + day; \
        float axx1 = fmaf(dax, xv[12] + xv[1], axx); \
        float ayy1 = fmaf(day, yv[12] + yv[1], ayy); \
        float axy1 = fmaf(-xv[1], yv[1], fmaf(xv[12], yv[12], axy)); \
        rg0[TT] = make_float2(ax, ax1);   s0.x += ax;  s0.y += ax1; \
        rg1[TT] = make_float2(ay, ay1);   s1.x += ay;  s1.y += ay1; \
        rg2[TT] = make_float2(axx, axx1); s2.x += axx; s2.y += axx1; \
        rg3[TT] = make_float2(ayy, ayy1); s3.x += ayy; s3.y += ayy1; \
        rg4[TT] = make_float2(axy, axy1); s4.x += axy; s4.y += axy1; \
        if (r >= h0 && r < h1) { \
            float e0 = fabsf(xv[6] - yv[6]); \
            l1acc += (e0 < 1.f) ? 0.5f * e0 * e0 : e0 - 0.5f; \
            float e1 = fabsf(xv[7] - yv[7]); \
            l1acc += (e1 < 1.f) ? 0.5f * e1 * e1 : e1 - 0.5f; \
        } \
    } \
    KA_FETCH(r + 3, (TT + 3) % 11) \
    if (t >= 10) { \
        const int hh = h0 + t - 10; \
        const int o2 = (pb + hh * W + w) >> 1; \
        g_bufB[0 * (NVOX/2) + o2] = __float22half2_rn(s0); \
        g_bufB[1 * (NVOX/2) + o2] = __float22half2_rn(s1); \
        g_bufB[2 * (NVOX/2) + o2] = __float22half2_rn(s2); \
        g_bufB[3 * (NVOX/2) + o2] = __float22half2_rn(s3); \
        g_bufB[4 * (NVOX/2) + o2] = __float22half2_rn(s4); \
        float2 z; \
        z = rg0[(TT + 1) % 11]; s0.x -= z.x; s0.y -= z.y; \
        z = rg1[(TT + 1) % 11]; s1.x -= z.x; s1.y -= z.y; \
        z = rg2[(TT + 1) % 11]; s2.x -= z.x; s2.y -= z.y; \
        z = rg3[(TT + 1) % 11]; s3.x -= z.x; s3.y -= z.y; \
        z = rg4[(TT + 1) % 11]; s4.x -= z.x; s4.y -= z.y; \
    } \
    r++; t++; }

__global__ __launch_bounds__(KA_THREADS, 4) void kA_wh(const float* __restrict__ x,
                                                       const float* __restrict__ y) {
    __shared__ __align__(16) float sx[11][SROW];
    __shared__ __align__(16) float sy[11][SROW];
    __shared__ float red[KA_THREADS];

    const int bx = blockIdx.x;
    const int seg = bx % HSEGS;
    const int d = (bx / HSEGS) % D;
    const int b = bx / (HSEGS * D);
    const int w2 = threadIdx.x;        // 0..79
    const int w = 2 * w2;

    const int h0 = seg * HSEG_LEN;
    const int h1 = h0 + HSEG_LEN;
    const int pb = (b * D + d) * HW;

    const uint32_t sx_base = (uint32_t)__cvta_generic_to_shared(&sx[0][0]);
    const uint32_t sy_base = (uint32_t)__cvta_generic_to_shared(&sy[0][0]);

    // zero pads once (cp.async never touches indices 0..5 / 166..171)
    if (w2 < 12) {
        int p = (w2 < 6) ? w2 : (160 + w2);
#pragma unroll
        for (int s = 0; s < 11; s++) { sx[s][p] = 0.f; sy[s][p] = 0.f; }
    }

    // prologue: fetch rows h0-5 .. h0-3 into slots 0..2
    KA_FETCH(h0 - 5, 0)
    KA_FETCH(h0 - 4, 1)
    KA_FETCH(h0 - 3, 2)

    float2 s0 = {0.f, 0.f}, s1 = {0.f, 0.f}, s2 = {0.f, 0.f};
    float2 s3 = {0.f, 0.f}, s4 = {0.f, 0.f};
    float l1acc = 0.f;
    float2 rg0[11], rg1[11], rg2[11], rg3[11], rg4[11];
    int r = h0 - 5;
    int t = 0;

#pragma unroll 1
    for (int tc = 0; tc < 4; tc++) {
        KA_STEP(0) KA_STEP(1) KA_STEP(2) KA_STEP(3) KA_STEP(4) KA_STEP(5)
        KA_STEP(6) KA_STEP(7) KA_STEP(8) KA_STEP(9) KA_STEP(10)
    }
    KA_STEP(0) KA_STEP(1) KA_STEP(2) KA_STEP(3) KA_STEP(4) KA_STEP(5)

    // deterministic block reduction of l1acc over 80 threads
    red[w2] = l1acc;
    __syncthreads();
    if (w2 < 40) red[w2] += red[w2 + 40];
    __syncthreads();
    if (w2 < 20) red[w2] += red[w2 + 20];
    __syncthreads();
    if (w2 < 10) red[w2] += red[w2 + 10];
    __syncthreads();
    if (w2 < 5) red[w2] += red[w2 + 5];
    __syncthreads();
    if (w2 == 0) {
        g_l1part[bx] = red[0] + red[1] + red[2] + red[3] + red[4];
    }
}
#undef KA_STEP
#undef KA_FETCH

// ---------------------------------------------------------------------------
// SSIM numerator/denominator (no division)
// ---------------------------------------------------------------------------
__device__ __forceinline__ void ssim_nd(float s0, float s1, float s2,
                                        float s3, float s4,
                                        float& num, float& den) {
    float mux = s0 * INV_WIN3;
    float muy = s1 * INV_WIN3;
    float mux2 = mux * mux;
    float muy2 = muy * muy;
    float muxy = mux * muy;
    float sxx = s2 * INV_WIN3 - mux2;
    float syy = s3 * INV_WIN3 - muy2;
    float sxy = s4 * INV_WIN3 - muxy;
    num = (2.f * muxy + C1F) * (2.f * sxy + C2F);
    den = (mux2 + muy2 + C1F) * (sxx + syy + C2F) + 1e-8f;
}

__device__ __forceinline__ float clip_loss(float ssim) {
    float loss = (1.f - ssim) * 0.5f;
    return fminf(fmaxf(loss, 0.f), 1.f);
}

// ---------------------------------------------------------------------------
// Kernel B: box-sum along D (running sums, leading+trailing edges; trailing
// hits L2) + SSIM (Montgomery-2: one division per 2 voxels) + block
// reduction. EXACT R8 geometry: half2 per thread, 2 h-rows per block,
// grid = B*(H/2)*KB_SEGS = 800 blocks, 160 threads.
// ---------------------------------------------------------------------------
__global__ __launch_bounds__(KB_THREADS) void kB_dpass_ssim() {
    __shared__ float red[KB_THREADS];

    const int bid = blockIdx.x;
    const int seg = bid % KB_SEGS;
    const int hq = (bid / KB_SEGS) % (H / KB_HBLK);
    const int b = bid / (KB_SEGS * (H / KB_HBLK));

    const int tid = threadIdx.x;
    const int w2 = tid % (W / 2);
    const int hr = tid / (W / 2);      // 0..1
    const int h = hq * KB_HBLK + hr;

    const int d0 = seg * KB_SEGLEN;
    const int col2 = (b * (D * HW) + h * W) / 2 + w2;
    const int st2 = HW / 2;

    const __half2* __restrict__ q0 = g_bufB + 0 * (NVOX / 2);
    const __half2* __restrict__ q1 = g_bufB + 1 * (NVOX / 2);
    const __half2* __restrict__ q2 = g_bufB + 2 * (NVOX / 2);
    const __half2* __restrict__ q3 = g_bufB + 3 * (NVOX / 2);
    const __half2* __restrict__ q4 = g_bufB + 4 * (NVOX / 2);

    float2 s0 = {0.f, 0.f}, s1 = {0.f, 0.f}, s2 = {0.f, 0.f};
    float2 s3 = {0.f, 0.f}, s4 = {0.f, 0.f};
    {
        int lo = d0 - 5; if (lo < 0) lo = 0;
        int hi = d0 + 5; if (hi > D - 1) hi = D - 1;
        for (int d = lo; d <= hi; d++) {
            int id = col2 + d * st2;
            float2 v;
            v = __half22float2(q0[id]); s0.x += v.x; s0.y += v.y;
            v = __half22float2(q1[id]); s1.x += v.x; s1.y += v.y;
            v = __half22float2(q2[id]); s2.x += v.x; s2.y += v.y;
            v = __half22float2(q3[id]); s3.x += v.x; s3.y += v.y;
            v = __half22float2(q4[id]); s4.x += v.x; s4.y += v.y;
        }
    }

    float acc = 0.f;
#pragma unroll 4
    for (int i = 0; i < KB_SEGLEN; i++) {
        const int d = d0 + i;
        const int dn = d + 6;
        const int dp = d - 5;

        float2 a0 = {0.f, 0.f}, a1 = {0.f, 0.f}, a2 = {0.f, 0.f};
        float2 a3 = {0.f, 0.f}, a4 = {0.f, 0.f};
        float2 b0 = {0.f, 0.f}, b1 = {0.f, 0.f}, b2 = {0.f, 0.f};
        float2 b3 = {0.f, 0.f}, b4 = {0.f, 0.f};
        if (dn < D) {
            int id = col2 + dn * st2;
            a0 = __half22float2(q0[id]); a1 = __half22float2(q1[id]);
            a2 = __half22float2(q2[id]); a3 = __half22float2(q3[id]);
            a4 = __half22float2(q4[id]);
        }
        if (dp >= 0) {
            int id = col2 + dp * st2;
            b0 = __half22float2(q0[id]); b1 = __half22float2(q1[id]);
            b2 = __half22float2(q2[id]); b3 = __half22float2(q3[id]);
            b4 = __half22float2(q4[id]);
        }

        // 2 SSIM ratios with a single reciprocal (Montgomery-2)
        {
            float nA, dA, nB, dB;
            ssim_nd(s0.x, s1.x, s2.x, s3.x, s4.x, nA, dA);
            ssim_nd(s0.y, s1.y, s2.y, s3.y, s4.y, nB, dB);
            float r = __fdividef(1.0f, dA * dB);
            acc += clip_loss(nA * dB * r);
            acc += clip_loss(nB * dA * r);
        }

        s0.x += a0.x - b0.x; s0.y += a0.y - b0.y;
        s1.x += a1.x - b1.x; s1.y += a1.y - b1.y;
        s2.x += a2.x - b2.x; s2.y += a2.y - b2.y;
        s3.x += a3.x - b3.x; s3.y += a3.y - b3.y;
        s4.x += a4.x - b4.x; s4.y += a4.y - b4.y;
    }

    // deterministic block reduction over 160 threads
    red[tid] = acc;
    __syncthreads();
    if (tid < 80) red[tid] += red[tid + 80];
    __syncthreads();
    if (tid < 40) red[tid] += red[tid + 40];
    __syncthreads();
    if (tid < 20) red[tid] += red[tid + 20];
    __syncthreads();
    if (tid < 10) red[tid] += red[tid + 10];
    __syncthreads();
    if (tid < 5) red[tid] += red[tid + 5];
    __syncthreads();
    if (tid == 0) {
        g_ssimpart[bid] = red[0] + red[1] + red[2] + red[3] + red[4];
    }
}

// ---------------------------------------------------------------------------
// Kernel C: final deterministic reduction.
// ---------------------------------------------------------------------------
__global__ __launch_bounds__(256) void kC_final(float* __restrict__ out) {
    __shared__ double sh[256];
    const int t = threadIdx.x;

    double a = 0.0;
    for (int i = t; i < A_BLOCKS; i += 256) a += (double)g_l1part[i];
    double bsum = 0.0;
    for (int i = t; i < KB_BLOCKS; i += 256) bsum += (double)g_ssimpart[i];

    sh[t] = a;
    __syncthreads();
#pragma unroll
    for (int s = 128; s > 0; s >>= 1) {
        if (t < s) sh[t] += sh[t + s];
        __syncthreads();
    }
    double l1sum = sh[0];
    __syncthreads();

    sh[t] = bsum;
    __syncthreads();
#pragma unroll
    for (int s = 128; s > 0; s >>= 1) {
        if (t < s) sh[t] += sh[t + s];
        __syncthreads();
    }

    if (t == 0) {
        double ssimsum = sh[0];
        double n = (double)NVOX;
        out[0] = (float)(0.85 * (ssimsum / n) + 0.15 * (l1sum / n));
    }
}

// ---------------------------------------------------------------------------
extern "C" void kernel_launch(void* const* d_in, const int* in_sizes, int n_in,
                              void* d_out, int out_size) {
    const float* pred = (const float*)d_in[0];
    const float* target = (const float*)d_in[1];
    float* out = (float*)d_out;

    kA_wh<<<A_BLOCKS, KA_THREADS>>>(pred, target);
    kB_dpass_ssim<<<KB_BLOCKS, KB_THREADS>>>();
    kC_final<<<1, 256>>>(out);
}

// round 16
// speedup vs baseline: 1.1978x; 1.0463x over previous
#include <cuda_runtime.h>
#include <cuda_fp16.h>
#include <cstdint>

// Fixed shapes
#define B 2
#define D 160
#define H 160
#define W 160
#define NVOX (B * D * H * W)          // 8,192,000
#define HW (H * W)                    // 25,600

#define HSEGS 4
#define HSEG_LEN (H / HSEGS)          // 40
#define A_BLOCKS (B * D * HSEGS)      // 1280
#define KA_THREADS 80                 // one float2 (2 outputs) per thread
#define SROW 172                      // 6 pad + 160 + 6 pad

#define KB_SEGS 5
#define KB_SEGLEN (D / KB_SEGS)       // 32
#define KB_HBLK 2
#define KB_THREADS 160                // 80 half2-lanes x 2 h-rows
#define KB_BLOCKS (B * (H / KB_HBLK) * KB_SEGS)  // 800

// SSIM constants (faithful: C1 = K1 / data_range^2)
#define C1F 5.9604644775390625e-10f   // 0.01 / 4096^2
#define C2F 1.7881393432617188e-09f   // 0.03 / 4096^2
#define INV_WIN3 (1.0f / 1331.0f)

// Intermediate: quantities 0-3 packed per w-pair as uint4 (4x half2 = 16B),
// quantity 4 in its own half2 plane. Same bytes as before, 2 ops not 5.
__device__ uint4 g_bufAB[NVOX / 2];       // 65.5 MB
__device__ __half2 g_buf4[NVOX / 2];      // 16.4 MB
__device__ float g_l1part[A_BLOCKS];
__device__ float g_ssimpart[KB_BLOCKS];
__device__ unsigned int g_done;           // zero-init; self-resets each run

__device__ __forceinline__ void cp_async8(uint32_t saddr, const void* g) {
    asm volatile("cp.async.ca.shared.global [%0], [%1], 8;" :: "r"(saddr), "l"(g));
}
__device__ __forceinline__ void cp_commit() {
    asm volatile("cp.async.commit_group;");
}
__device__ __forceinline__ void cp_wait2() {
    asm volatile("cp.async.wait_group 2;");
}

// ---------------------------------------------------------------------------
// Kernel A: fused W+H box sums (x, y, x^2, y^2, xy), 2 outputs per thread.
// 11-slot cp.async staging pipeline (depth 3), float2 taps, incremental
// second output, fp32 register ring (frozen R12 config). Stores: one STG.128
// (q0-q3 packed) + one STG.32 (q4).
// ---------------------------------------------------------------------------
#define KA_FETCH(ROW, SLOT) { \
    const int _r = (ROW); \
    if (_r >= 0 && _r < H) { \
        cp_async8(sx_base + (SLOT) * (SROW * 4) + (6 + w) * 4, x + pb + _r * W + w); \
        cp_async8(sy_base + (SLOT) * (SROW * 4) + (6 + w) * 4, y + pb + _r * W + w); \
    } else { \
        *(float2*)&sx[SLOT][6 + w] = make_float2(0.f, 0.f); \
        *(float2*)&sy[SLOT][6 + w] = make_float2(0.f, 0.f); \
    } \
    cp_commit(); }

#define KA_STEP(TT) { \
    cp_wait2(); \
    __syncthreads(); \
    { \
        const float2* rx2 = (const float2*)&sx[TT][w]; \
        const float2* ry2 = (const float2*)&sy[TT][w]; \
        float xv[14], yv[14]; \
        _Pragma("unroll") \
        for (int i = 0; i < 7; i++) { \
            float2 t2 = rx2[i]; xv[2*i] = t2.x; xv[2*i+1] = t2.y; \
            float2 u2 = ry2[i]; yv[2*i] = u2.x; yv[2*i+1] = u2.y; \
        } \
        float ax = xv[1], ay = yv[1]; \
        float axx = xv[1]*xv[1], ayy = yv[1]*yv[1], axy = xv[1]*yv[1]; \
        _Pragma("unroll") \
        for (int i = 2; i <= 11; i++) { \
            ax += xv[i]; ay += yv[i]; \
            axx = fmaf(xv[i], xv[i], axx); \
            ayy = fmaf(yv[i], yv[i], ayy); \
            axy = fmaf(xv[i], yv[i], axy); \
        } \
        float dax = xv[12] - xv[1], day = yv[12] - yv[1]; \
        float ax1 = ax + dax, ay1 = ay + day; \
        float axx1 = fmaf(dax, xv[12] + xv[1], axx); \
        float ayy1 = fmaf(day, yv[12] + yv[1], ayy); \
        float axy1 = fmaf(-xv[1], yv[1], fmaf(xv[12], yv[12], axy)); \
        rg0[TT] = make_float2(ax, ax1);   s0.x += ax;  s0.y += ax1; \
        rg1[TT] = make_float2(ay, ay1);   s1.x += ay;  s1.y += ay1; \
        rg2[TT] = make_float2(axx, axx1); s2.x += axx; s2.y += axx1; \
        rg3[TT] = make_float2(ayy, ayy1); s3.x += ayy; s3.y += ayy1; \
        rg4[TT] = make_float2(axy, axy1); s4.x += axy; s4.y += axy1; \
        if (r >= h0 && r < h1) { \
            float e0 = fabsf(xv[6] - yv[6]); \
            l1acc += (e0 < 1.f) ? 0.5f * e0 * e0 : e0 - 0.5f; \
            float e1 = fabsf(xv[7] - yv[7]); \
            l1acc += (e1 < 1.f) ? 0.5f * e1 * e1 : e1 - 0.5f; \
        } \
    } \
    KA_FETCH(r + 3, (TT + 3) % 11) \
    if (t >= 10) { \
        const int hh = h0 + t - 10; \
        const int o2 = (pb + hh * W + w) >> 1; \
        __half2 p0 = __float22half2_rn(s0); \
        __half2 p1 = __float22half2_rn(s1); \
        __half2 p2 = __float22half2_rn(s2); \
        __half2 p3 = __float22half2_rn(s3); \
        uint4 pk; \
        pk.x = *(const uint32_t*)&p0; pk.y = *(const uint32_t*)&p1; \
        pk.z = *(const uint32_t*)&p2; pk.w = *(const uint32_t*)&p3; \
        g_bufAB[o2] = pk; \
        g_buf4[o2] = __float22half2_rn(s4); \
        float2 z; \
        z = rg0[(TT + 1) % 11]; s0.x -= z.x; s0.y -= z.y; \
        z = rg1[(TT + 1) % 11]; s1.x -= z.x; s1.y -= z.y; \
        z = rg2[(TT + 1) % 11]; s2.x -= z.x; s2.y -= z.y; \
        z = rg3[(TT + 1) % 11]; s3.x -= z.x; s3.y -= z.y; \
        z = rg4[(TT + 1) % 11]; s4.x -= z.x; s4.y -= z.y; \
    } \
    r++; t++; }

__global__ __launch_bounds__(KA_THREADS, 4) void kA_wh(const float* __restrict__ x,
                                                       const float* __restrict__ y) {
    __shared__ __align__(16) float sx[11][SROW];
    __shared__ __align__(16) float sy[11][SROW];
    __shared__ float red[KA_THREADS];

    const int bx = blockIdx.x;
    const int seg = bx % HSEGS;
    const int d = (bx / HSEGS) % D;
    const int b = bx / (HSEGS * D);
    const int w2 = threadIdx.x;        // 0..79
    const int w = 2 * w2;

    const int h0 = seg * HSEG_LEN;
    const int h1 = h0 + HSEG_LEN;
    const int pb = (b * D + d) * HW;

    const uint32_t sx_base = (uint32_t)__cvta_generic_to_shared(&sx[0][0]);
    const uint32_t sy_base = (uint32_t)__cvta_generic_to_shared(&sy[0][0]);

    // zero pads once (cp.async never touches indices 0..5 / 166..171)
    if (w2 < 12) {
        int p = (w2 < 6) ? w2 : (160 + w2);
#pragma unroll
        for (int s = 0; s < 11; s++) { sx[s][p] = 0.f; sy[s][p] = 0.f; }
    }

    // prologue: fetch rows h0-5 .. h0-3 into slots 0..2
    KA_FETCH(h0 - 5, 0)
    KA_FETCH(h0 - 4, 1)
    KA_FETCH(h0 - 3, 2)

    float2 s0 = {0.f, 0.f}, s1 = {0.f, 0.f}, s2 = {0.f, 0.f};
    float2 s3 = {0.f, 0.f}, s4 = {0.f, 0.f};
    float l1acc = 0.f;
    float2 rg0[11], rg1[11], rg2[11], rg3[11], rg4[11];
    int r = h0 - 5;
    int t = 0;

#pragma unroll 1
    for (int tc = 0; tc < 4; tc++) {
        KA_STEP(0) KA_STEP(1) KA_STEP(2) KA_STEP(3) KA_STEP(4) KA_STEP(5)
        KA_STEP(6) KA_STEP(7) KA_STEP(8) KA_STEP(9) KA_STEP(10)
    }
    KA_STEP(0) KA_STEP(1) KA_STEP(2) KA_STEP(3) KA_STEP(4) KA_STEP(5)

    // deterministic block reduction of l1acc over 80 threads
    red[w2] = l1acc;
    __syncthreads();
    if (w2 < 40) red[w2] += red[w2 + 40];
    __syncthreads();
    if (w2 < 20) red[w2] += red[w2 + 20];
    __syncthreads();
    if (w2 < 10) red[w2] += red[w2 + 10];
    __syncthreads();
    if (w2 < 5) red[w2] += red[w2 + 5];
    __syncthreads();
    if (w2 == 0) {
        g_l1part[bx] = red[0] + red[1] + red[2] + red[3] + red[4];
    }
}
#undef KA_STEP
#undef KA_FETCH

// ---------------------------------------------------------------------------
// SSIM numerator/denominator (no division)
// ---------------------------------------------------------------------------
__device__ __forceinline__ void ssim_nd(float s0, float s1, float s2,
                                        float s3, float s4,
                                        float& num, float& den) {
    float mux = s0 * INV_WIN3;
    float muy = s1 * INV_WIN3;
    float mux2 = mux * mux;
    float muy2 = muy * muy;
    float muxy = mux * muy;
    float sxx = s2 * INV_WIN3 - mux2;
    float syy = s3 * INV_WIN3 - muy2;
    float sxy = s4 * INV_WIN3 - muxy;
    num = (2.f * muxy + C1F) * (2.f * sxy + C2F);
    den = (mux2 + muy2 + C1F) * (sxx + syy + C2F) + 1e-8f;
}

__device__ __forceinline__ float clip_loss(float ssim) {
    float loss = (1.f - ssim) * 0.5f;
    return fminf(fmaxf(loss, 0.f), 1.f);
}

// unpack a packed plane sample: uint4 -> 4x float2, plus half2 -> float2
#define UNPK(U, V0, V1, V2, V3) { \
    V0 = __half22float2(*(const __half2*)&(U).x); \
    V1 = __half22float2(*(const __half2*)&(U).y); \
    V2 = __half22float2(*(const __half2*)&(U).z); \
    V3 = __half22float2(*(const __half2*)&(U).w); }

// ---------------------------------------------------------------------------
// Kernel B: box-sum along D (running sums, leading+trailing edges) + SSIM
// (Montgomery-2) + block reduction + LAST-BLOCK final reduction (kC merged).
// Loads: one LDG.128 + one LDG.32 per plane-edge (was 5 LDG.32).
// R8 geometry: half2 per thread, 2 h-rows/block, 800 blocks, 160 threads.
// ---------------------------------------------------------------------------
__global__ __launch_bounds__(KB_THREADS) void kB_dpass_ssim(float* __restrict__ out) {
    __shared__ float red[KB_THREADS];
    __shared__ double dsh[KB_THREADS];
    __shared__ bool amLast;

    const int bid = blockIdx.x;
    const int seg = bid % KB_SEGS;
    const int hq = (bid / KB_SEGS) % (H / KB_HBLK);
    const int b = bid / (KB_SEGS * (H / KB_HBLK));

    const int tid = threadIdx.x;
    const int w2 = tid % (W / 2);
    const int hr = tid / (W / 2);      // 0..1
    const int h = hq * KB_HBLK + hr;

    const int d0 = seg * KB_SEGLEN;
    const int col2 = (b * (D * HW) + h * W) / 2 + w2;
    const int st2 = HW / 2;

    const uint4* __restrict__ qAB = g_bufAB;
    const __half2* __restrict__ q4 = g_buf4;

    float2 s0 = {0.f, 0.f}, s1 = {0.f, 0.f}, s2 = {0.f, 0.f};
    float2 s3 = {0.f, 0.f}, s4 = {0.f, 0.f};
    {
        int lo = d0 - 5; if (lo < 0) lo = 0;
        int hi = d0 + 5; if (hi > D - 1) hi = D - 1;
        for (int d = lo; d <= hi; d++) {
            int id = col2 + d * st2;
            uint4 u = qAB[id];
            float2 v0, v1, v2, v3;
            UNPK(u, v0, v1, v2, v3)
            float2 v4 = __half22float2(q4[id]);
            s0.x += v0.x; s0.y += v0.y;
            s1.x += v1.x; s1.y += v1.y;
            s2.x += v2.x; s2.y += v2.y;
            s3.x += v3.x; s3.y += v3.y;
            s4.x += v4.x; s4.y += v4.y;
        }
    }

    float acc = 0.f;
#pragma unroll 4
    for (int i = 0; i < KB_SEGLEN; i++) {
        const int d = d0 + i;
        const int dn = d + 6;
        const int dp = d - 5;

        float2 a0 = {0.f, 0.f}, a1 = {0.f, 0.f}, a2 = {0.f, 0.f};
        float2 a3 = {0.f, 0.f}, a4 = {0.f, 0.f};
        float2 b0 = {0.f, 0.f}, b1 = {0.f, 0.f}, b2 = {0.f, 0.f};
        float2 b3 = {0.f, 0.f}, b4 = {0.f, 0.f};
        if (dn < D) {
            int id = col2 + dn * st2;
            uint4 u = qAB[id];
            UNPK(u, a0, a1, a2, a3)
            a4 = __half22float2(q4[id]);
        }
        if (dp >= 0) {
            int id = col2 + dp * st2;
            uint4 u = qAB[id];
            UNPK(u, b0, b1, b2, b3)
            b4 = __half22float2(q4[id]);
        }

        // 2 SSIM ratios with a single reciprocal (Montgomery-2)
        {
            float nA, dA, nB, dB;
            ssim_nd(s0.x, s1.x, s2.x, s3.x, s4.x, nA, dA);
            ssim_nd(s0.y, s1.y, s2.y, s3.y, s4.y, nB, dB);
            float r = __fdividef(1.0f, dA * dB);
            acc += clip_loss(nA * dB * r);
            acc += clip_loss(nB * dA * r);
        }

        s0.x += a0.x - b0.x; s0.y += a0.y - b0.y;
        s1.x += a1.x - b1.x; s1.y += a1.y - b1.y;
        s2.x += a2.x - b2.x; s2.y += a2.y - b2.y;
        s3.x += a3.x - b3.x; s3.y += a3.y - b3.y;
        s4.x += a4.x - b4.x; s4.y += a4.y - b4.y;
    }

    // deterministic block reduction over 160 threads
    red[tid] = acc;
    __syncthreads();
    if (tid < 80) red[tid] += red[tid + 80];
    __syncthreads();
    if (tid < 40) red[tid] += red[tid + 40];
    __syncthreads();
    if (tid < 20) red[tid] += red[tid + 20];
    __syncthreads();
    if (tid < 10) red[tid] += red[tid + 10];
    __syncthreads();
    if (tid < 5) red[tid] += red[tid + 5];
    __syncthreads();
    if (tid == 0) {
        g_ssimpart[bid] = red[0] + red[1] + red[2] + red[3] + red[4];
    }

    // ---- last-block final reduction (deterministic; replaces kC) ----
    __threadfence();
    if (tid == 0) {
        unsigned int v = atomicAdd(&g_done, 1u);
        amLast = (v == (unsigned int)(KB_BLOCKS - 1));
    }
    __syncthreads();
    if (!amLast) return;

    double a = 0.0;
    for (int i = tid; i < A_BLOCKS; i += KB_THREADS) a += (double)g_l1part[i];
    dsh[tid] = a;
    __syncthreads();
    if (tid < 80) dsh[tid] += dsh[tid + 80];
    __syncthreads();
    if (tid < 40) dsh[tid] += dsh[tid + 40];
    __syncthreads();
    if (tid < 20) dsh[tid] += dsh[tid + 20];
    __syncthreads();
    if (tid < 10) dsh[tid] += dsh[tid + 10];
    __syncthreads();
    if (tid < 5) dsh[tid] += dsh[tid + 5];
    __syncthreads();
    double l1sum = dsh[0] + dsh[1] + dsh[2] + dsh[3] + dsh[4];
    __syncthreads();

    double s = 0.0;
    for (int i = tid; i < KB_BLOCKS; i += KB_THREADS) s += (double)g_ssimpart[i];
    dsh[tid] = s;
    __syncthreads();
    if (tid < 80) dsh[tid] += dsh[tid + 80];
    __syncthreads();
    if (tid < 40) dsh[tid] += dsh[tid + 40];
    __syncthreads();
    if (tid < 20) dsh[tid] += dsh[tid + 20];
    __syncthreads();
    if (tid < 10) dsh[tid] += dsh[tid + 10];
    __syncthreads();
    if (tid < 5) dsh[tid] += dsh[tid + 5];
    __syncthreads();

    if (tid == 0) {
        double ssimsum = dsh[0] + dsh[1] + dsh[2] + dsh[3] + dsh[4];
        double n = (double)NVOX;
        out[0] = (float)(0.85 * (ssimsum / n) + 0.15 * (l1sum / n));
        g_done = 0;   // reset for next graph replay
    }
}
#undef UNPK

// ---------------------------------------------------------------------------
extern "C" void kernel_launch(void* const* d_in, const int* in_sizes, int n_in,
                              void* d_out, int out_size) {
    const float* pred = (const float*)d_in[0];
    const float* target = (const float*)d_in[1];
    float* out = (float*)d_out;

    kA_wh<<<A_BLOCKS, KA_THREADS>>>(pred, target);
    kB_dpass_ssim<<<KB_BLOCKS, KB_THREADS>>>(out);
}